// round 16
// baseline (speedup 1.0000x reference)
#include <cuda_runtime.h>

// LIF recurrence: v = alpha*v + beta*c; spike = (v >= 1); v = spike ? 0 : v.
//
// R15 resubmit of R14's proposal (previous round was an infra failure, kernel
// never ran). Base: best-known config (123.5us kernel, 76.3% DRAM): 1024x32
// launch, 4-slot x U=16 ring, refill interleaved per-element. Six configs
// pinned at 72-76% DRAM -> read concurrency exhausted; limiter is the mixed
// 1-read:2-write DRAM stream. Single change vs R14: stores use .wt
// (write-through) instead of .cs. With .cs, 512 MB of output sits dirty in
// L2 and reaches DRAM as bursty eviction-driven writebacks; .wt pushes full
// coalesced 128B lines straight through at store time, smoothing the DRAM
// write stream and freeing L2 from dirty-line cycling.

// Bit-identical arithmetic to the reference:
// ALPHA = float(np.exp(-1/20)), BETA = float(1 - ALPHA_double).
#define ALPHA_F ((float)0.95122942450071400910)
#define BETA_F  ((float)0.04877057549928599090)

template<int T, int N, int U>
__global__ void __launch_bounds__(32)
lif_wt(const float* __restrict__ cur, const float* __restrict__ v0,
       float* __restrict__ spikes, float* __restrict__ volts)
{
    const int n = blockIdx.x * blockDim.x + threadIdx.x;   // one thread per neuron
    float v = v0[n];

    const float* p  = cur    + n;
    float*       ps = spikes + n;
    float*       pv = volts  + n;

    static_assert(T % U == 0 && (T / U) % 4 == 0, "phase count must divide by 4");
    constexpr int ITERS = T / U;   // 128 phases for T=2048, U=16

    float buf[4][U];

    // Prologue: fill all 4 ring slots (phases 0..3).
#pragma unroll
    for (int k = 0; k < 4; ++k)
#pragma unroll
        for (int u = 0; u < U; ++u)
            buf[k][u] = __ldcs(p + (size_t)(k * U + u) * N);
    p += (size_t)4 * U * N;        // refill pointer = phase 4

    // Main loop: consume element u, immediately issue its phase+4 refill,
    // then write-through both outputs. Loads issue continuously; each refill
    // lands ~4 phases (>1500 cyc) before its consumer.
    for (int i = 0; i < ITERS - 4; i += 4) {
#pragma unroll
        for (int k = 0; k < 4; ++k) {
#pragma unroll
            for (int u = 0; u < U; ++u) {
                const float c = buf[k][u];
                buf[k][u] = __ldcs(p + (size_t)u * N);   // refill (used 4 phases later)
                v = fmaf(ALPHA_F, v, BETA_F * c);
                const bool sp = (v >= 1.0f);
                __stwt(ps + (size_t)u * N, sp ? 1.0f : 0.0f);
                v = sp ? 0.0f : v;                        // V_RESET = 0
                __stwt(pv + (size_t)u * N, v);
            }
            ps += (size_t)U * N;  pv += (size_t)U * N;  p += (size_t)U * N;
        }
    }

    // Epilogue: last 4 phases, no refills.
#pragma unroll
    for (int k = 0; k < 4; ++k) {
#pragma unroll
        for (int u = 0; u < U; ++u) {
            v = fmaf(ALPHA_F, v, BETA_F * buf[k][u]);
            const bool sp = (v >= 1.0f);
            __stwt(ps + (size_t)u * N, sp ? 1.0f : 0.0f);
            v = sp ? 0.0f : v;
            __stwt(pv + (size_t)u * N, v);
        }
        ps += (size_t)U * N;  pv += (size_t)U * N;
    }
}

// Generic fallback (any T, N).
__global__ void lif_generic(const float* __restrict__ cur, const float* __restrict__ v0,
                            float* __restrict__ spikes, float* __restrict__ volts,
                            int T, int N)
{
    int n = blockIdx.x * blockDim.x + threadIdx.x;
    if (n >= N) return;
    float v = v0[n];
    size_t idx = (size_t)n;
    for (int t = 0; t < T; ++t) {
        float c = __ldcs(cur + idx);
        v = fmaf(ALPHA_F, v, BETA_F * c);
        const bool sp = (v >= 1.0f);
        __stcs(spikes + idx, sp ? 1.0f : 0.0f);
        v = sp ? 0.0f : v;
        __stcs(volts + idx, v);
        idx += (size_t)N;
    }
}

extern "C" void kernel_launch(void* const* d_in, const int* in_sizes, int n_in,
                              void* d_out, int out_size)
{
    // metadata order: currents (T*N), v0 (N)
    const float* cur = (const float*)d_in[0];
    const float* v0  = (const float*)d_in[1];

    const int N = in_sizes[1];
    const int T = in_sizes[0] / N;

    float* out    = (float*)d_out;
    float* spikes = out;                          // first T*N elements
    float* volts  = out + (size_t)T * (size_t)N;  // second T*N elements

    if (T == 2048 && N == 32768) {
        // Proven launch shape: 1024 blocks x 32 threads (1024 warps, single wave).
        lif_wt<2048, 32768, 16><<<1024, 32>>>(cur, v0, spikes, volts);
    } else {
        const int threads = 128;
        lif_generic<<<(N + threads - 1) / threads, threads>>>(cur, v0, spikes, volts, T, N);
    }
}